// round 10
// baseline (speedup 1.0000x reference)
#include <cuda_runtime.h>
#include <cuda_bf16.h>
#include <cstdint>
#include <cstddef>

#define N_MAX 50000
#define E_MAX 800000
#define FIN   256
#define FOUT  128
#define AST   72   // padded smem row stride (bf16 elems): fragment banks all distinct

// ---------------------------------------------------------------------------
// Scratch (static device globals — no runtime allocation allowed)
// ---------------------------------------------------------------------------
__device__ float g_m[(size_t)N_MAX * FOUT];   // mean message
__device__ float g_v[(size_t)N_MAX * FOUT];   // var  message
__device__ int   g_cnt[N_MAX];
__device__ int   g_off[N_MAX + 1];
__device__ int   g_cur[N_MAX];
__device__ int   g_ssrc[E_MAX];
__device__ float g_norm1[N_MAX];
// Transposed + bf16-split weights: [n][k] layout, FOUT x FIN each
__device__ __nv_bfloat16 g_wmh[(size_t)FOUT * FIN];
__device__ __nv_bfloat16 g_wml[(size_t)FOUT * FIN];
__device__ __nv_bfloat16 g_wvh[(size_t)FOUT * FIN];
__device__ __nv_bfloat16 g_wvl[(size_t)FOUT * FIN];

__device__ __forceinline__ uint32_t pack2bf(float a, float b) {
    uint32_t ua = (uint32_t)__bfloat16_as_ushort(__float2bfloat16_rn(a));
    uint32_t ub = (uint32_t)__bfloat16_as_ushort(__float2bfloat16_rn(b));
    return (ub << 16) | ua;
}

// m16n8k16 row.col bf16 MMA, f32 accumulate (sm_80+, no 'a' target needed)
__device__ __forceinline__ void mma_bf16(float* d,
    uint32_t a0, uint32_t a1, uint32_t a2, uint32_t a3,
    uint32_t b0, uint32_t b1)
{
    asm volatile(
        "mma.sync.aligned.m16n8k16.row.col.f32.bf16.bf16.f32 "
        "{%0,%1,%2,%3}, {%4,%5,%6,%7}, {%8,%9}, {%0,%1,%2,%3};\n"
        : "+f"(d[0]), "+f"(d[1]), "+f"(d[2]), "+f"(d[3])
        : "r"(a0), "r"(a1), "r"(a2), "r"(a3), "r"(b0), "r"(b1));
}

// ---------------------------------------------------------------------------
// Degree histogram / scan / scatter
// ---------------------------------------------------------------------------
__global__ void deg_kernel(const int* __restrict__ dst, int E) {
    for (int i = blockIdx.x * blockDim.x + threadIdx.x; i < E;
         i += gridDim.x * blockDim.x)
        atomicAdd(&g_cnt[dst[i]], 1);
}

__global__ void scan_kernel(int n, int E) {
    __shared__ int part[1024];
    const int t = threadIdx.x;
    const int chunk = (n + 1023) / 1024;
    const int beg = t * chunk;
    const int end = (beg + chunk < n) ? beg + chunk : n;
    int s = 0;
    for (int i = beg; i < end; i++) s += g_cnt[i];
    part[t] = s;
    __syncthreads();
    for (int off = 1; off < 1024; off <<= 1) {
        int tmp = (t >= off) ? part[t - off] : 0;
        __syncthreads();
        part[t] += tmp;
        __syncthreads();
    }
    int run = part[t] - s;
    for (int i = beg; i < end; i++) {
        g_off[i] = run;
        g_cur[i] = run;
        int c = g_cnt[i];
        run += c;
        float d = (float)((c < 1) ? 1 : c);
        g_norm1[i] = rsqrtf(d);
    }
    if (t == 1023) g_off[n] = E;
}

__global__ void scatter_kernel(const int* __restrict__ src,
                               const int* __restrict__ dst, int E) {
    for (int i = blockIdx.x * blockDim.x + threadIdx.x; i < E;
         i += gridDim.x * blockDim.x) {
        int d = dst[i];
        int pos = atomicAdd(&g_cur[d], 1);
        g_ssrc[pos] = src[i];
    }
}

// ---------------------------------------------------------------------------
// Weight prep: transpose to [n][k] and split fp32 -> bf16 hi + lo
// ---------------------------------------------------------------------------
__global__ void wprep_kernel(const float* __restrict__ Wm,
                             const float* __restrict__ Wv) {
    int idx = blockIdx.x * blockDim.x + threadIdx.x;  // over FIN*FOUT
    if (idx >= FIN * FOUT) return;
    int k = idx / FOUT, nn = idx % FOUT;
    float wm = Wm[idx], wv = Wv[idx];
    __nv_bfloat16 mh = __float2bfloat16_rn(wm);
    __nv_bfloat16 ml = __float2bfloat16_rn(wm - __bfloat162float(mh));
    __nv_bfloat16 vh = __float2bfloat16_rn(wv);
    __nv_bfloat16 vl = __float2bfloat16_rn(wv - __bfloat162float(vh));
    size_t o = (size_t)nn * FIN + k;
    g_wmh[o] = mh; g_wml[o] = ml;
    g_wvh[o] = vh; g_wvl[o] = vl;
}

// ---------------------------------------------------------------------------
// mma.sync split-bf16 dual-GEMM + message epilogue.
// 128x128 tile per CTA, 256 threads, warps as 4(m) x 2(n) -> 32x64 warp tiles.
// K in 4 chunks of 64 (outer loop NOT unrolled to bound code size).
// Split precision: Ahi*Bhi + Ahi*Blo + Alo*Bhi.
// SMEM rows padded to AST=72 bf16 so every fragment LDS.32 is conflict-free.
// ---------------------------------------------------------------------------
#define SM_AH  0
#define SM_AL  (SM_AH + 128 * AST * 2)
#define SM_MH  (SM_AL + 128 * AST * 2)
#define SM_ML  (SM_MH + 128 * AST * 2)
#define SM_VH  (SM_ML + 128 * AST * 2)
#define SM_VL  (SM_VH + 128 * AST * 2)
#define SMEM_TOTAL (SM_VL + 128 * AST * 2)   // 110592 B

__global__ void __launch_bounds__(256, 1) gemm_mma_kernel(
    const float* __restrict__ feat, int n)
{
    extern __shared__ char smem[];
    const int tid  = threadIdx.x;
    const int wid  = tid >> 5;
    const int lane = tid & 31;
    const int gid  = lane >> 2;      // group id 0..7
    const int tig  = lane & 3;       // thread in group
    const int wm   = wid >> 1;       // warp m 0..3
    const int wn   = wid & 1;        // warp n 0..1
    const int m0   = blockIdx.x * 128;

    float accM[2][8][4];
    float accV[2][8][4];
#pragma unroll
    for (int mt = 0; mt < 2; mt++)
#pragma unroll
        for (int nt = 0; nt < 8; nt++)
#pragma unroll
            for (int r = 0; r < 4; r++) { accM[mt][nt][r] = 0.f; accV[mt][nt][r] = 0.f; }

#pragma unroll 1
    for (int c = 0; c < 4; c++) {
        // ---- A chunk: feat[:, c*64 .. +64) fp32 -> bf16 hi/lo in padded smem
#pragma unroll 1
        for (int idx = tid; idx < 2048; idx += 256) {   // 128 rows x 16 float4
            int row = idx >> 4;
            int c4  = (idx & 15) * 4;
            float4 f = make_float4(0.f, 0.f, 0.f, 0.f);
            if (m0 + row < n)
                f = *(const float4*)(feat + (size_t)(m0 + row) * FIN + c * 64 + c4);
            float hx = __bfloat162float(__float2bfloat16_rn(f.x));
            float hy = __bfloat162float(__float2bfloat16_rn(f.y));
            float hz = __bfloat162float(__float2bfloat16_rn(f.z));
            float hw = __bfloat162float(__float2bfloat16_rn(f.w));
            uint2 hi = make_uint2(pack2bf(f.x, f.y), pack2bf(f.z, f.w));
            uint2 lo = make_uint2(pack2bf(f.x - hx, f.y - hy),
                                  pack2bf(f.z - hz, f.w - hw));
            int eo = row * AST + c4;
            *(uint2*)(smem + SM_AH + eo * 2) = hi;
            *(uint2*)(smem + SM_AL + eo * 2) = lo;
        }
        // ---- W chunks: [n][k] bf16, cols c*64 .. +64
        {
            const __nv_bfloat16* srcs[4] = {g_wmh, g_wml, g_wvh, g_wvl};
            const int offs[4] = {SM_MH, SM_ML, SM_VH, SM_VL};
#pragma unroll 1
            for (int t4 = 0; t4 < 4; t4++) {
#pragma unroll 1
                for (int idx = tid; idx < 2048; idx += 256) {
                    int nn = idx >> 4;
                    int k4 = (idx & 15) * 4;
                    uint2 w = *(const uint2*)(srcs[t4] + (size_t)nn * FIN + c * 64 + k4);
                    *(uint2*)(smem + offs[t4] + (nn * AST + k4) * 2) = w;
                }
            }
        }
        __syncthreads();

#pragma unroll
        for (int ks = 0; ks < 4; ks++) {
            const int k0 = ks * 16;
            // ---- A fragments (hi and lo), 2 m-tiles
            uint32_t ah[2][4], al[2][4];
#pragma unroll
            for (int mt = 0; mt < 2; mt++) {
                int base = (wm * 32 + mt * 16 + gid) * AST + k0 + 2 * tig;
                ah[mt][0] = *(const uint32_t*)(smem + SM_AH + base * 2);
                ah[mt][1] = *(const uint32_t*)(smem + SM_AH + (base + 8 * AST) * 2);
                ah[mt][2] = *(const uint32_t*)(smem + SM_AH + (base + 8) * 2);
                ah[mt][3] = *(const uint32_t*)(smem + SM_AH + (base + 8 * AST + 8) * 2);
                al[mt][0] = *(const uint32_t*)(smem + SM_AL + base * 2);
                al[mt][1] = *(const uint32_t*)(smem + SM_AL + (base + 8 * AST) * 2);
                al[mt][2] = *(const uint32_t*)(smem + SM_AL + (base + 8) * 2);
                al[mt][3] = *(const uint32_t*)(smem + SM_AL + (base + 8 * AST + 8) * 2);
            }
#pragma unroll
            for (int nt = 0; nt < 8; nt++) {
                int nb = (wn * 64 + nt * 8 + gid) * AST + k0 + 2 * tig;
                // mean
                {
                    uint32_t bh0 = *(const uint32_t*)(smem + SM_MH + nb * 2);
                    uint32_t bh1 = *(const uint32_t*)(smem + SM_MH + (nb + 8) * 2);
                    uint32_t bl0 = *(const uint32_t*)(smem + SM_ML + nb * 2);
                    uint32_t bl1 = *(const uint32_t*)(smem + SM_ML + (nb + 8) * 2);
#pragma unroll
                    for (int mt = 0; mt < 2; mt++) {
                        mma_bf16(accM[mt][nt], ah[mt][0], ah[mt][1], ah[mt][2], ah[mt][3], bh0, bh1);
                        mma_bf16(accM[mt][nt], ah[mt][0], ah[mt][1], ah[mt][2], ah[mt][3], bl0, bl1);
                        mma_bf16(accM[mt][nt], al[mt][0], al[mt][1], al[mt][2], al[mt][3], bh0, bh1);
                    }
                }
                // var
                {
                    uint32_t bh0 = *(const uint32_t*)(smem + SM_VH + nb * 2);
                    uint32_t bh1 = *(const uint32_t*)(smem + SM_VH + (nb + 8) * 2);
                    uint32_t bl0 = *(const uint32_t*)(smem + SM_VL + nb * 2);
                    uint32_t bl1 = *(const uint32_t*)(smem + SM_VL + (nb + 8) * 2);
#pragma unroll
                    for (int mt = 0; mt < 2; mt++) {
                        mma_bf16(accV[mt][nt], ah[mt][0], ah[mt][1], ah[mt][2], ah[mt][3], bh0, bh1);
                        mma_bf16(accV[mt][nt], ah[mt][0], ah[mt][1], ah[mt][2], ah[mt][3], bl0, bl1);
                        mma_bf16(accV[mt][nt], al[mt][0], al[mt][1], al[mt][2], al[mt][3], bh0, bh1);
                    }
                }
            }
        }
        __syncthreads();   // smem reused next chunk
    }

    // ---- epilogue: relu, attention, src-norm -> per-node messages ----
#pragma unroll
    for (int mt = 0; mt < 2; mt++) {
#pragma unroll
        for (int rr = 0; rr < 2; rr++) {
            int row  = wm * 32 + mt * 16 + rr * 8 + gid;
            int node = m0 + row;
            if (node >= n) continue;
            float n1 = g_norm1[node];
            float n2 = n1 * n1;
            float* pm = g_m + (size_t)node * FOUT;
            float* pv = g_v + (size_t)node * FOUT;
#pragma unroll
            for (int nt = 0; nt < 8; nt++) {
                int col = wn * 64 + nt * 8 + 2 * tig;
                float M0 = accM[mt][nt][rr * 2 + 0];
                float M1 = accM[mt][nt][rr * 2 + 1];
                float V0 = accV[mt][nt][rr * 2 + 0];
                float V1 = accV[mt][nt][rr * 2 + 1];
                float mean0 = fmaxf(M0, 0.f), var0 = fmaxf(V0, 0.f);
                float mean1 = fmaxf(M1, 0.f), var1 = fmaxf(V1, 0.f);
                float att0 = __expf(-var0), att1 = __expf(-var1);
                float2 mo = make_float2(mean0 * att0 * n1, mean1 * att1 * n1);
                float2 vo = make_float2(var0 * att0 * att0 * n2,
                                        var1 * att1 * att1 * n2);
                *(float2*)(pm + col) = mo;
                *(float2*)(pv + col) = vo;
            }
        }
    }
}

// ---------------------------------------------------------------------------
// CSR aggregation: one warp per dst node.
// ---------------------------------------------------------------------------
__global__ void agg_csr_kernel(float* __restrict__ out_mean,
                               float* __restrict__ out_var,
                               int n)
{
    int w    = (int)((blockIdx.x * (size_t)blockDim.x + threadIdx.x) >> 5);
    int lane = threadIdx.x & 31;
    if (w >= n) return;

    int b = g_off[w];
    int e = g_off[w + 1];

    float4 am = make_float4(0.0f, 0.0f, 0.0f, 0.0f);
    float4 av = make_float4(0.0f, 0.0f, 0.0f, 0.0f);

    int i = b;
    for (; i + 2 <= e; i += 2) {
        int s0 = __ldg(g_ssrc + i);
        int s1 = __ldg(g_ssrc + i + 1);
        const float4 m0 = *(const float4*)(g_m + (size_t)s0 * FOUT + lane * 4);
        const float4 v0 = *(const float4*)(g_v + (size_t)s0 * FOUT + lane * 4);
        const float4 m1 = *(const float4*)(g_m + (size_t)s1 * FOUT + lane * 4);
        const float4 v1 = *(const float4*)(g_v + (size_t)s1 * FOUT + lane * 4);
        am.x += m0.x + m1.x; am.y += m0.y + m1.y;
        am.z += m0.z + m1.z; am.w += m0.w + m1.w;
        av.x += v0.x + v1.x; av.y += v0.y + v1.y;
        av.z += v0.z + v1.z; av.w += v0.w + v1.w;
    }
    if (i < e) {
        int s0 = __ldg(g_ssrc + i);
        const float4 m0 = *(const float4*)(g_m + (size_t)s0 * FOUT + lane * 4);
        const float4 v0 = *(const float4*)(g_v + (size_t)s0 * FOUT + lane * 4);
        am.x += m0.x; am.y += m0.y; am.z += m0.z; am.w += m0.w;
        av.x += v0.x; av.y += v0.y; av.z += v0.z; av.w += v0.w;
    }

    float n1 = g_norm1[w];
    float n2 = n1 * n1;
    am.x *= n1; am.y *= n1; am.z *= n1; am.w *= n1;
    av.x *= n2; av.y *= n2; av.z *= n2; av.w *= n2;

    *(float4*)(out_mean + (size_t)w * FOUT + lane * 4) = am;
    *(float4*)(out_var  + (size_t)w * FOUT + lane * 4) = av;
}

// ---------------------------------------------------------------------------
// Launch
// ---------------------------------------------------------------------------
extern "C" void kernel_launch(void* const* d_in, const int* in_sizes, int n_in,
                              void* d_out, int out_size)
{
    const float* feat = (const float*)d_in[0];
    const int*   esrc = (const int*)d_in[1];
    const int*   edst = (const int*)d_in[2];
    const float* Wm   = (const float*)d_in[3];
    const float* Wv   = (const float*)d_in[4];
    float* out = (float*)d_out;

    int n = in_sizes[0] / FIN;   // 50000
    int E = in_sizes[1];         // 800000

    float* out_mean = out;
    float* out_var  = out + (size_t)n * FOUT;

    void* cnt_ptr = nullptr;
    cudaGetSymbolAddress(&cnt_ptr, g_cnt);
    cudaMemsetAsync(cnt_ptr, 0, (size_t)N_MAX * sizeof(int));

    deg_kernel<<<592, 256>>>(edst, E);
    scan_kernel<<<1, 1024>>>(n, E);
    scatter_kernel<<<592, 256>>>(esrc, edst, E);

    wprep_kernel<<<(FIN * FOUT + 255) / 256, 256>>>(Wm, Wv);

    cudaFuncSetAttribute(gemm_mma_kernel,
                         cudaFuncAttributeMaxDynamicSharedMemorySize,
                         SMEM_TOTAL);
    gemm_mma_kernel<<<(n + 127) / 128, 256, SMEM_TOTAL>>>(feat, n);

    int warps_per_block = 256 / 32;
    int agg_blocks = (n + warps_per_block - 1) / warps_per_block;
    agg_csr_kernel<<<agg_blocks, 256>>>(out_mean, out_var, n);
}

// round 13
// speedup vs baseline: 1.1767x; 1.1767x over previous
#include <cuda_runtime.h>
#include <cuda_fp16.h>
#include <cstdint>
#include <cstddef>

#define N_MAX 50000
#define E_MAX 800000
#define FIN   256
#define FOUT  128
#define AST   72   // padded smem row stride (fp16 elems): fragment banks all distinct

// ---------------------------------------------------------------------------
// Scratch (static device globals — no runtime allocation allowed)
// ---------------------------------------------------------------------------
__device__ float g_m[(size_t)N_MAX * FOUT];   // mean message
__device__ float g_v[(size_t)N_MAX * FOUT];   // var  message
__device__ int   g_cnt[N_MAX];
__device__ int   g_off[N_MAX + 1];
__device__ int   g_cur[N_MAX];
__device__ int   g_ssrc[E_MAX];
__device__ float g_norm1[N_MAX];
// Transposed fp16 weights: [n][k] layout, FOUT x FIN each (single precision term)
__device__ __half g_wmh[(size_t)FOUT * FIN];
__device__ __half g_wvh[(size_t)FOUT * FIN];

__device__ __forceinline__ uint32_t pack2h(float a, float b) {
    __half2 h = __floats2half2_rn(a, b);
    return *(uint32_t*)&h;
}

// m16n8k16 row.col fp16 MMA, f32 accumulate (sm_80+)
__device__ __forceinline__ void mma_f16(float* d,
    uint32_t a0, uint32_t a1, uint32_t a2, uint32_t a3,
    uint32_t b0, uint32_t b1)
{
    asm volatile(
        "mma.sync.aligned.m16n8k16.row.col.f32.f16.f16.f32 "
        "{%0,%1,%2,%3}, {%4,%5,%6,%7}, {%8,%9}, {%0,%1,%2,%3};\n"
        : "+f"(d[0]), "+f"(d[1]), "+f"(d[2]), "+f"(d[3])
        : "r"(a0), "r"(a1), "r"(a2), "r"(a3), "r"(b0), "r"(b1));
}

// ---------------------------------------------------------------------------
// Degree histogram / scan / scatter
// ---------------------------------------------------------------------------
__global__ void deg_kernel(const int* __restrict__ dst, int E) {
    for (int i = blockIdx.x * blockDim.x + threadIdx.x; i < E;
         i += gridDim.x * blockDim.x)
        atomicAdd(&g_cnt[dst[i]], 1);
}

__global__ void scan_kernel(int n, int E) {
    __shared__ int part[1024];
    const int t = threadIdx.x;
    const int chunk = (n + 1023) / 1024;
    const int beg = t * chunk;
    const int end = (beg + chunk < n) ? beg + chunk : n;
    int s = 0;
    for (int i = beg; i < end; i++) s += g_cnt[i];
    part[t] = s;
    __syncthreads();
    for (int off = 1; off < 1024; off <<= 1) {
        int tmp = (t >= off) ? part[t - off] : 0;
        __syncthreads();
        part[t] += tmp;
        __syncthreads();
    }
    int run = part[t] - s;
    for (int i = beg; i < end; i++) {
        g_off[i] = run;
        g_cur[i] = run;
        int c = g_cnt[i];
        run += c;
        float d = (float)((c < 1) ? 1 : c);
        g_norm1[i] = rsqrtf(d);
    }
    if (t == 1023) g_off[n] = E;
}

__global__ void scatter_kernel(const int* __restrict__ src,
                               const int* __restrict__ dst, int E) {
    for (int i = blockIdx.x * blockDim.x + threadIdx.x; i < E;
         i += gridDim.x * blockDim.x) {
        int d = dst[i];
        int pos = atomicAdd(&g_cur[d], 1);
        g_ssrc[pos] = src[i];
    }
}

// ---------------------------------------------------------------------------
// Weight prep: transpose to [n][k], fp32 -> fp16 (single term; err ~2^-12)
// ---------------------------------------------------------------------------
__global__ void wprep_kernel(const float* __restrict__ Wm,
                             const float* __restrict__ Wv) {
    int idx = blockIdx.x * blockDim.x + threadIdx.x;  // over FIN*FOUT
    if (idx >= FIN * FOUT) return;
    int k = idx / FOUT, nn = idx % FOUT;
    size_t o = (size_t)nn * FIN + k;
    g_wmh[o] = __float2half_rn(Wm[idx]);
    g_wvh[o] = __float2half_rn(Wv[idx]);
}

// ---------------------------------------------------------------------------
// mma.sync fp16 dual-GEMM + message epilogue.
// 128x128 tile per CTA, 256 threads, warps as 4(m) x 2(n) -> 32x64 warp tiles.
// K in 4 chunks of 64. Precision: A = Ah + Al (fp16 pair), W = fp16 single
// -> D = Ah*W + Al*W, output err ~1e-4 (<< 1e-3 gate). 2 MMAs per acc per
// k-step (was 3 with bf16 split): 8192 HMMAs/CTA.
// SMEM rows padded to AST=72 fp16 so every fragment LDS.32 is conflict-free.
// ---------------------------------------------------------------------------
#define SM_AH  0
#define SM_AL  (SM_AH + 128 * AST * 2)
#define SM_MH  (SM_AL + 128 * AST * 2)
#define SM_VH  (SM_MH + 128 * AST * 2)
#define SMEM_TOTAL (SM_VH + 128 * AST * 2)   // 73728 B

__global__ void __launch_bounds__(256, 1) gemm_mma_kernel(
    const float* __restrict__ feat, int n)
{
    extern __shared__ char smem[];
    const int tid  = threadIdx.x;
    const int wid  = tid >> 5;
    const int lane = tid & 31;
    const int gid  = lane >> 2;      // group id 0..7
    const int tig  = lane & 3;       // thread in group
    const int wm   = wid >> 1;       // warp m 0..3
    const int wn   = wid & 1;        // warp n 0..1
    const int m0   = blockIdx.x * 128;

    float accM[2][8][4];
    float accV[2][8][4];
#pragma unroll
    for (int mt = 0; mt < 2; mt++)
#pragma unroll
        for (int nt = 0; nt < 8; nt++)
#pragma unroll
            for (int r = 0; r < 4; r++) { accM[mt][nt][r] = 0.f; accV[mt][nt][r] = 0.f; }

#pragma unroll 1
    for (int c = 0; c < 4; c++) {
        // ---- A chunk: feat[:, c*64 .. +64) fp32 -> fp16 hi/lo in padded smem
#pragma unroll 1
        for (int idx = tid; idx < 2048; idx += 256) {   // 128 rows x 16 float4
            int row = idx >> 4;
            int c4  = (idx & 15) * 4;
            float4 f = make_float4(0.f, 0.f, 0.f, 0.f);
            if (m0 + row < n)
                f = *(const float4*)(feat + (size_t)(m0 + row) * FIN + c * 64 + c4);
            float hx = __half2float(__float2half_rn(f.x));
            float hy = __half2float(__float2half_rn(f.y));
            float hz = __half2float(__float2half_rn(f.z));
            float hw = __half2float(__float2half_rn(f.w));
            uint2 hi = make_uint2(pack2h(f.x, f.y), pack2h(f.z, f.w));
            uint2 lo = make_uint2(pack2h(f.x - hx, f.y - hy),
                                  pack2h(f.z - hz, f.w - hw));
            int eo = row * AST + c4;
            *(uint2*)(smem + SM_AH + eo * 2) = hi;
            *(uint2*)(smem + SM_AL + eo * 2) = lo;
        }
        // ---- W chunks: [n][k] fp16, cols c*64 .. +64 (2 arrays now)
        {
            const __half* srcs[2] = {g_wmh, g_wvh};
            const int offs[2] = {SM_MH, SM_VH};
#pragma unroll 1
            for (int t2 = 0; t2 < 2; t2++) {
#pragma unroll 1
                for (int idx = tid; idx < 2048; idx += 256) {
                    int nn = idx >> 4;
                    int k4 = (idx & 15) * 4;
                    uint2 w = *(const uint2*)(srcs[t2] + (size_t)nn * FIN + c * 64 + k4);
                    *(uint2*)(smem + offs[t2] + (nn * AST + k4) * 2) = w;
                }
            }
        }
        __syncthreads();

#pragma unroll
        for (int ks = 0; ks < 4; ks++) {
            const int k0 = ks * 16;
            // ---- A fragments (hi and lo), 2 m-tiles
            uint32_t ah[2][4], al[2][4];
#pragma unroll
            for (int mt = 0; mt < 2; mt++) {
                int base = (wm * 32 + mt * 16 + gid) * AST + k0 + 2 * tig;
                ah[mt][0] = *(const uint32_t*)(smem + SM_AH + base * 2);
                ah[mt][1] = *(const uint32_t*)(smem + SM_AH + (base + 8 * AST) * 2);
                ah[mt][2] = *(const uint32_t*)(smem + SM_AH + (base + 8) * 2);
                ah[mt][3] = *(const uint32_t*)(smem + SM_AH + (base + 8 * AST + 8) * 2);
                al[mt][0] = *(const uint32_t*)(smem + SM_AL + base * 2);
                al[mt][1] = *(const uint32_t*)(smem + SM_AL + (base + 8 * AST) * 2);
                al[mt][2] = *(const uint32_t*)(smem + SM_AL + (base + 8) * 2);
                al[mt][3] = *(const uint32_t*)(smem + SM_AL + (base + 8 * AST + 8) * 2);
            }
#pragma unroll
            for (int nt = 0; nt < 8; nt++) {
                int nb = (wn * 64 + nt * 8 + gid) * AST + k0 + 2 * tig;
                // mean
                {
                    uint32_t b0 = *(const uint32_t*)(smem + SM_MH + nb * 2);
                    uint32_t b1 = *(const uint32_t*)(smem + SM_MH + (nb + 8) * 2);
#pragma unroll
                    for (int mt = 0; mt < 2; mt++) {
                        mma_f16(accM[mt][nt], ah[mt][0], ah[mt][1], ah[mt][2], ah[mt][3], b0, b1);
                        mma_f16(accM[mt][nt], al[mt][0], al[mt][1], al[mt][2], al[mt][3], b0, b1);
                    }
                }
                // var
                {
                    uint32_t b0 = *(const uint32_t*)(smem + SM_VH + nb * 2);
                    uint32_t b1 = *(const uint32_t*)(smem + SM_VH + (nb + 8) * 2);
#pragma unroll
                    for (int mt = 0; mt < 2; mt++) {
                        mma_f16(accV[mt][nt], ah[mt][0], ah[mt][1], ah[mt][2], ah[mt][3], b0, b1);
                        mma_f16(accV[mt][nt], al[mt][0], al[mt][1], al[mt][2], al[mt][3], b0, b1);
                    }
                }
            }
        }
        __syncthreads();   // smem reused next chunk
    }

    // ---- epilogue: relu, attention, src-norm -> per-node messages ----
#pragma unroll
    for (int mt = 0; mt < 2; mt++) {
#pragma unroll
        for (int rr = 0; rr < 2; rr++) {
            int row  = wm * 32 + mt * 16 + rr * 8 + gid;
            int node = m0 + row;
            if (node >= n) continue;
            float n1 = g_norm1[node];
            float n2 = n1 * n1;
            float* pm = g_m + (size_t)node * FOUT;
            float* pv = g_v + (size_t)node * FOUT;
#pragma unroll
            for (int nt = 0; nt < 8; nt++) {
                int col = wn * 64 + nt * 8 + 2 * tig;
                float M0 = accM[mt][nt][rr * 2 + 0];
                float M1 = accM[mt][nt][rr * 2 + 1];
                float V0 = accV[mt][nt][rr * 2 + 0];
                float V1 = accV[mt][nt][rr * 2 + 1];
                float mean0 = fmaxf(M0, 0.f), var0 = fmaxf(V0, 0.f);
                float mean1 = fmaxf(M1, 0.f), var1 = fmaxf(V1, 0.f);
                float att0 = __expf(-var0), att1 = __expf(-var1);
                float2 mo = make_float2(mean0 * att0 * n1, mean1 * att1 * n1);
                float2 vo = make_float2(var0 * att0 * att0 * n2,
                                        var1 * att1 * att1 * n2);
                *(float2*)(pm + col) = mo;
                *(float2*)(pv + col) = vo;
            }
        }
    }
}

// ---------------------------------------------------------------------------
// CSR aggregation: one warp per dst node.
// ---------------------------------------------------------------------------
__global__ void agg_csr_kernel(float* __restrict__ out_mean,
                               float* __restrict__ out_var,
                               int n)
{
    int w    = (int)((blockIdx.x * (size_t)blockDim.x + threadIdx.x) >> 5);
    int lane = threadIdx.x & 31;
    if (w >= n) return;

    int b = g_off[w];
    int e = g_off[w + 1];

    float4 am = make_float4(0.0f, 0.0f, 0.0f, 0.0f);
    float4 av = make_float4(0.0f, 0.0f, 0.0f, 0.0f);

    int i = b;
    for (; i + 2 <= e; i += 2) {
        int s0 = __ldg(g_ssrc + i);
        int s1 = __ldg(g_ssrc + i + 1);
        const float4 m0 = *(const float4*)(g_m + (size_t)s0 * FOUT + lane * 4);
        const float4 v0 = *(const float4*)(g_v + (size_t)s0 * FOUT + lane * 4);
        const float4 m1 = *(const float4*)(g_m + (size_t)s1 * FOUT + lane * 4);
        const float4 v1 = *(const float4*)(g_v + (size_t)s1 * FOUT + lane * 4);
        am.x += m0.x + m1.x; am.y += m0.y + m1.y;
        am.z += m0.z + m1.z; am.w += m0.w + m1.w;
        av.x += v0.x + v1.x; av.y += v0.y + v1.y;
        av.z += v0.z + v1.z; av.w += v0.w + v1.w;
    }
    if (i < e) {
        int s0 = __ldg(g_ssrc + i);
        const float4 m0 = *(const float4*)(g_m + (size_t)s0 * FOUT + lane * 4);
        const float4 v0 = *(const float4*)(g_v + (size_t)s0 * FOUT + lane * 4);
        am.x += m0.x; am.y += m0.y; am.z += m0.z; am.w += m0.w;
        av.x += v0.x; av.y += v0.y; av.z += v0.z; av.w += v0.w;
    }

    float n1 = g_norm1[w];
    float n2 = n1 * n1;
    am.x *= n1; am.y *= n1; am.z *= n1; am.w *= n1;
    av.x *= n2; av.y *= n2; av.z *= n2; av.w *= n2;

    *(float4*)(out_mean + (size_t)w * FOUT + lane * 4) = am;
    *(float4*)(out_var  + (size_t)w * FOUT + lane * 4) = av;
}

// ---------------------------------------------------------------------------
// Launch — ordered so the GEMM is launch #5 (memset counted), which is the
// launch ncu's "-s 5 -c 1" capture lands on. Dependencies preserved:
// gemm needs wprep + scan(norm1); scatter needs scan(cur); agg needs both.
// ---------------------------------------------------------------------------
extern "C" void kernel_launch(void* const* d_in, const int* in_sizes, int n_in,
                              void* d_out, int out_size)
{
    const float* feat = (const float*)d_in[0];
    const int*   esrc = (const int*)d_in[1];
    const int*   edst = (const int*)d_in[2];
    const float* Wm   = (const float*)d_in[3];
    const float* Wv   = (const float*)d_in[4];
    float* out = (float*)d_out;

    int n = in_sizes[0] / FIN;   // 50000
    int E = in_sizes[1];         // 800000

    float* out_mean = out;
    float* out_var  = out + (size_t)n * FOUT;

    void* cnt_ptr = nullptr;
    cudaGetSymbolAddress(&cnt_ptr, g_cnt);
    cudaMemsetAsync(cnt_ptr, 0, (size_t)N_MAX * sizeof(int));      // launch 1

    wprep_kernel<<<(FIN * FOUT + 255) / 256, 256>>>(Wm, Wv);       // launch 2
    deg_kernel<<<592, 256>>>(edst, E);                             // launch 3
    scan_kernel<<<1, 1024>>>(n, E);                                // launch 4

    cudaFuncSetAttribute(gemm_mma_kernel,
                         cudaFuncAttributeMaxDynamicSharedMemorySize,
                         SMEM_TOTAL);
    gemm_mma_kernel<<<(n + 127) / 128, 256, SMEM_TOTAL>>>(feat, n); // launch 5

    scatter_kernel<<<592, 256>>>(esrc, edst, E);                   // launch 6

    int warps_per_block = 256 / 32;
    int agg_blocks = (n + warps_per_block - 1) / warps_per_block;
    agg_csr_kernel<<<agg_blocks, 256>>>(out_mean, out_var, n);     // launch 7
}

// round 15
// speedup vs baseline: 1.5101x; 1.2833x over previous
#include <cuda_runtime.h>
#include <cuda_fp16.h>
#include <cstdint>
#include <cstddef>

#define N_MAX 50000
#define E_MAX 800000
#define FIN   256
#define FOUT  128
#define AST   72   // padded smem row stride (fp16 elems)

// ---------------------------------------------------------------------------
// Scratch (static device globals — no runtime allocation allowed)
// ---------------------------------------------------------------------------
__device__ float g_m[(size_t)N_MAX * FOUT];   // mean message
__device__ float g_v[(size_t)N_MAX * FOUT];   // var  message
__device__ int   g_cnt[N_MAX];
__device__ int   g_off[N_MAX + 1];
__device__ int   g_cur[N_MAX];
__device__ int   g_ssrc[E_MAX];
__device__ float g_norm1[N_MAX];
// Transposed fp16 weights: [n][k] layout, FOUT x FIN each
__device__ __half g_wmh[(size_t)FOUT * FIN];
__device__ __half g_wvh[(size_t)FOUT * FIN];

__device__ __forceinline__ uint32_t pack2h(float a, float b) {
    __half2 h = __floats2half2_rn(a, b);
    return *(uint32_t*)&h;
}

// m16n8k16 row.col fp16 MMA, f32 accumulate (sm_80+)
__device__ __forceinline__ void mma_f16(float* d,
    uint32_t a0, uint32_t a1, uint32_t a2, uint32_t a3,
    uint32_t b0, uint32_t b1)
{
    asm volatile(
        "mma.sync.aligned.m16n8k16.row.col.f32.f16.f16.f32 "
        "{%0,%1,%2,%3}, {%4,%5,%6,%7}, {%8,%9}, {%0,%1,%2,%3};\n"
        : "+f"(d[0]), "+f"(d[1]), "+f"(d[2]), "+f"(d[3])
        : "r"(a0), "r"(a1), "r"(a2), "r"(a3), "r"(b0), "r"(b1));
}

// ---------------------------------------------------------------------------
// Degree histogram / scan / scatter
// ---------------------------------------------------------------------------
__global__ void deg_kernel(const int* __restrict__ dst, int E) {
    for (int i = blockIdx.x * blockDim.x + threadIdx.x; i < E;
         i += gridDim.x * blockDim.x)
        atomicAdd(&g_cnt[dst[i]], 1);
}

__global__ void scan_kernel(int n, int E) {
    __shared__ int part[1024];
    const int t = threadIdx.x;
    const int chunk = (n + 1023) / 1024;
    const int beg = t * chunk;
    const int end = (beg + chunk < n) ? beg + chunk : n;
    int s = 0;
    for (int i = beg; i < end; i++) s += g_cnt[i];
    part[t] = s;
    __syncthreads();
    for (int off = 1; off < 1024; off <<= 1) {
        int tmp = (t >= off) ? part[t - off] : 0;
        __syncthreads();
        part[t] += tmp;
        __syncthreads();
    }
    int run = part[t] - s;
    for (int i = beg; i < end; i++) {
        g_off[i] = run;
        g_cur[i] = run;
        int c = g_cnt[i];
        run += c;
        float d = (float)((c < 1) ? 1 : c);
        g_norm1[i] = rsqrtf(d);
    }
    if (t == 1023) g_off[n] = E;
}

__global__ void scatter_kernel(const int* __restrict__ src,
                               const int* __restrict__ dst, int E) {
    for (int i = blockIdx.x * blockDim.x + threadIdx.x; i < E;
         i += gridDim.x * blockDim.x) {
        int d = dst[i];
        int pos = atomicAdd(&g_cur[d], 1);
        g_ssrc[pos] = src[i];
    }
}

// ---------------------------------------------------------------------------
// Weight prep: transpose to [n][k], fp32 -> fp16 (single term)
// ---------------------------------------------------------------------------
__global__ void wprep_kernel(const float* __restrict__ Wm,
                             const float* __restrict__ Wv) {
    int idx = blockIdx.x * blockDim.x + threadIdx.x;
    if (idx >= FIN * FOUT) return;
    int k = idx / FOUT, nn = idx % FOUT;
    size_t o = (size_t)nn * FIN + k;
    g_wmh[o] = __float2half_rn(Wm[idx]);
    g_wvh[o] = __float2half_rn(Wv[idx]);
}

// ---------------------------------------------------------------------------
// mma.sync fp16 dual-GEMM + message epilogue, v2: 512 threads, 4m x 4n warps
// (32x32 warp tiles), double-buffered smem. Per chunk: next A prefetched to
// registers + next W streamed via cp.async DURING the MMA phase; A converted
// (fp32 -> fp16 hi/lo) and stored after MMAs. 8192 HMMAs/CTA, 64 acc/thread.
// ---------------------------------------------------------------------------
#define SM_AH  0
#define SM_AL  18432
#define SM_MH  36864
#define SM_VH  55296
#define BUF_B  73728
#define SMEM_TOTAL (2 * BUF_B)   // 147456 B

__global__ void __launch_bounds__(512, 1) gemm_mma_kernel(
    const float* __restrict__ feat, int n)
{
    extern __shared__ char smem[];
    const int tid  = threadIdx.x;
    const int wid  = tid >> 5;
    const int lane = tid & 31;
    const int gid  = lane >> 2;
    const int tig  = lane & 3;
    const int wm   = wid >> 2;       // warp m 0..3
    const int wn   = wid & 3;        // warp n 0..3
    const int m0   = blockIdx.x * 128;

    float accM[2][4][4];
    float accV[2][4][4];
#pragma unroll
    for (int mt = 0; mt < 2; mt++)
#pragma unroll
        for (int nt = 0; nt < 4; nt++)
#pragma unroll
            for (int r = 0; r < 4; r++) { accM[mt][nt][r] = 0.f; accV[mt][nt][r] = 0.f; }

    float4 pf[4];   // A prefetch registers (4 float4 per thread per chunk)

    // ---- helpers as lambdas ----
    auto loadA = [&](int c) {
#pragma unroll
        for (int i = 0; i < 4; i++) {
            int idx = tid + i * 512;
            int row = idx >> 4;
            int c4  = (idx & 15) * 4;
            pf[i] = make_float4(0.f, 0.f, 0.f, 0.f);
            if (m0 + row < n)
                pf[i] = *(const float4*)(feat + (size_t)(m0 + row) * FIN + c * 64 + c4);
        }
    };
    auto cpasyncW = [&](int c, int buf) {
#pragma unroll
        for (int t2 = 0; t2 < 2; t2++) {
            const __half* src = t2 ? g_wvh : g_wmh;
            int off = buf * BUF_B + (t2 ? SM_VH : SM_MH);
#pragma unroll
            for (int i = 0; i < 4; i++) {
                int idx = tid + i * 512;
                int nn = idx >> 4;
                int k4 = (idx & 15) * 4;
                uint32_t saddr = (uint32_t)__cvta_generic_to_shared(
                    smem + off + (nn * AST + k4) * 2);
                const void* gaddr = src + (size_t)nn * FIN + c * 64 + k4;
                asm volatile("cp.async.ca.shared.global [%0], [%1], 8;"
                             :: "r"(saddr), "l"(gaddr));
            }
        }
        asm volatile("cp.async.commit_group;");
    };
    auto storeA = [&](int buf) {
#pragma unroll
        for (int i = 0; i < 4; i++) {
            int idx = tid + i * 512;
            int row = idx >> 4;
            int c4  = (idx & 15) * 4;
            float4 f = pf[i];
            float hx = __half2float(__float2half_rn(f.x));
            float hy = __half2float(__float2half_rn(f.y));
            float hz = __half2float(__float2half_rn(f.z));
            float hw = __half2float(__float2half_rn(f.w));
            uint2 hi = make_uint2(pack2h(f.x, f.y), pack2h(f.z, f.w));
            uint2 lo = make_uint2(pack2h(f.x - hx, f.y - hy),
                                  pack2h(f.z - hz, f.w - hw));
            int eo = buf * BUF_B + (row * AST + c4) * 2;
            *(uint2*)(smem + SM_AH + eo) = hi;
            *(uint2*)(smem + SM_AL + eo) = lo;
        }
    };

    // ---- prologue: fill buffer 0 with chunk 0 ----
    loadA(0);
    cpasyncW(0, 0);
    storeA(0);
    asm volatile("cp.async.wait_group 0;");
    __syncthreads();

    int buf = 0;
#pragma unroll 1
    for (int c = 0; c < 4; c++) {
        int nbuf = buf ^ 1;
        if (c < 3) {            // kick off next chunk: LDGs + cp.async in flight
            loadA(c + 1);
            cpasyncW(c + 1, nbuf);
        }

        const int bo = buf * BUF_B;
#pragma unroll
        for (int ks = 0; ks < 4; ks++) {
            const int k0 = ks * 16;
            uint32_t ah[2][4], al[2][4];
#pragma unroll
            for (int mt = 0; mt < 2; mt++) {
                int base = bo + ((wm * 32 + mt * 16 + gid) * AST + k0 + 2 * tig) * 2;
                ah[mt][0] = *(const uint32_t*)(smem + SM_AH + base);
                ah[mt][1] = *(const uint32_t*)(smem + SM_AH + base + 8 * AST * 2);
                ah[mt][2] = *(const uint32_t*)(smem + SM_AH + base + 16);
                ah[mt][3] = *(const uint32_t*)(smem + SM_AH + base + 8 * AST * 2 + 16);
                al[mt][0] = *(const uint32_t*)(smem + SM_AL + base);
                al[mt][1] = *(const uint32_t*)(smem + SM_AL + base + 8 * AST * 2);
                al[mt][2] = *(const uint32_t*)(smem + SM_AL + base + 16);
                al[mt][3] = *(const uint32_t*)(smem + SM_AL + base + 8 * AST * 2 + 16);
            }
#pragma unroll
            for (int nt = 0; nt < 4; nt++) {
                int nb = bo + ((wn * 32 + nt * 8 + gid) * AST + k0 + 2 * tig) * 2;
                {
                    uint32_t b0 = *(const uint32_t*)(smem + SM_MH + nb);
                    uint32_t b1 = *(const uint32_t*)(smem + SM_MH + nb + 16);
#pragma unroll
                    for (int mt = 0; mt < 2; mt++) {
                        mma_f16(accM[mt][nt], ah[mt][0], ah[mt][1], ah[mt][2], ah[mt][3], b0, b1);
                        mma_f16(accM[mt][nt], al[mt][0], al[mt][1], al[mt][2], al[mt][3], b0, b1);
                    }
                }
                {
                    uint32_t b0 = *(const uint32_t*)(smem + SM_VH + nb);
                    uint32_t b1 = *(const uint32_t*)(smem + SM_VH + nb + 16);
#pragma unroll
                    for (int mt = 0; mt < 2; mt++) {
                        mma_f16(accV[mt][nt], ah[mt][0], ah[mt][1], ah[mt][2], ah[mt][3], b0, b1);
                        mma_f16(accV[mt][nt], al[mt][0], al[mt][1], al[mt][2], al[mt][3], b0, b1);
                    }
                }
            }
        }

        if (c < 3) {
            storeA(nbuf);       // convert + STS after MMAs (LDGs completed by now)
            asm volatile("cp.async.wait_group 0;");
        }
        __syncthreads();
        buf = nbuf;
    }

    // ---- epilogue: relu, attention, src-norm -> per-node messages ----
#pragma unroll
    for (int mt = 0; mt < 2; mt++) {
#pragma unroll
        for (int rr = 0; rr < 2; rr++) {
            int row  = wm * 32 + mt * 16 + rr * 8 + gid;
            int node = m0 + row;
            if (node >= n) continue;
            float n1 = g_norm1[node];
            float n2 = n1 * n1;
            float* pm = g_m + (size_t)node * FOUT;
            float* pv = g_v + (size_t)node * FOUT;
#pragma unroll
            for (int nt = 0; nt < 4; nt++) {
                int col = wn * 32 + nt * 8 + 2 * tig;
                float M0 = accM[mt][nt][rr * 2 + 0];
                float M1 = accM[mt][nt][rr * 2 + 1];
                float V0 = accV[mt][nt][rr * 2 + 0];
                float V1 = accV[mt][nt][rr * 2 + 1];
                float mean0 = fmaxf(M0, 0.f), var0 = fmaxf(V0, 0.f);
                float mean1 = fmaxf(M1, 0.f), var1 = fmaxf(V1, 0.f);
                float att0 = __expf(-var0), att1 = __expf(-var1);
                float2 mo = make_float2(mean0 * att0 * n1, mean1 * att1 * n1);
                float2 vo = make_float2(var0 * att0 * att0 * n2,
                                        var1 * att1 * att1 * n2);
                *(float2*)(pm + col) = mo;
                *(float2*)(pv + col) = vo;
            }
        }
    }
}

// ---------------------------------------------------------------------------
// CSR aggregation: one warp per dst node.
// ---------------------------------------------------------------------------
__global__ void agg_csr_kernel(float* __restrict__ out_mean,
                               float* __restrict__ out_var,
                               int n)
{
    int w    = (int)((blockIdx.x * (size_t)blockDim.x + threadIdx.x) >> 5);
    int lane = threadIdx.x & 31;
    if (w >= n) return;

    int b = g_off[w];
    int e = g_off[w + 1];

    float4 am = make_float4(0.0f, 0.0f, 0.0f, 0.0f);
    float4 av = make_float4(0.0f, 0.0f, 0.0f, 0.0f);

    int i = b;
    for (; i + 2 <= e; i += 2) {
        int s0 = __ldg(g_ssrc + i);
        int s1 = __ldg(g_ssrc + i + 1);
        const float4 m0 = *(const float4*)(g_m + (size_t)s0 * FOUT + lane * 4);
        const float4 v0 = *(const float4*)(g_v + (size_t)s0 * FOUT + lane * 4);
        const float4 m1 = *(const float4*)(g_m + (size_t)s1 * FOUT + lane * 4);
        const float4 v1 = *(const float4*)(g_v + (size_t)s1 * FOUT + lane * 4);
        am.x += m0.x + m1.x; am.y += m0.y + m1.y;
        am.z += m0.z + m1.z; am.w += m0.w + m1.w;
        av.x += v0.x + v1.x; av.y += v0.y + v1.y;
        av.z += v0.z + v1.z; av.w += v0.w + v1.w;
    }
    if (i < e) {
        int s0 = __ldg(g_ssrc + i);
        const float4 m0 = *(const float4*)(g_m + (size_t)s0 * FOUT + lane * 4);
        const float4 v0 = *(const float4*)(g_v + (size_t)s0 * FOUT + lane * 4);
        am.x += m0.x; am.y += m0.y; am.z += m0.z; am.w += m0.w;
        av.x += v0.x; av.y += v0.y; av.z += v0.z; av.w += v0.w;
    }

    float n1 = g_norm1[w];
    float n2 = n1 * n1;
    am.x *= n1; am.y *= n1; am.z *= n1; am.w *= n1;
    av.x *= n2; av.y *= n2; av.z *= n2; av.w *= n2;

    *(float4*)(out_mean + (size_t)w * FOUT + lane * 4) = am;
    *(float4*)(out_var  + (size_t)w * FOUT + lane * 4) = av;
}

// ---------------------------------------------------------------------------
// Launch — GEMM kept at launch #5 for ncu's "-s 5 -c 1" capture.
// ---------------------------------------------------------------------------
extern "C" void kernel_launch(void* const* d_in, const int* in_sizes, int n_in,
                              void* d_out, int out_size)
{
    const float* feat = (const float*)d_in[0];
    const int*   esrc = (const int*)d_in[1];
    const int*   edst = (const int*)d_in[2];
    const float* Wm   = (const float*)d_in[3];
    const float* Wv   = (const float*)d_in[4];
    float* out = (float*)d_out;

    int n = in_sizes[0] / FIN;   // 50000
    int E = in_sizes[1];         // 800000

    float* out_mean = out;
    float* out_var  = out + (size_t)n * FOUT;

    void* cnt_ptr = nullptr;
    cudaGetSymbolAddress(&cnt_ptr, g_cnt);
    cudaMemsetAsync(cnt_ptr, 0, (size_t)N_MAX * sizeof(int));      // launch 1

    wprep_kernel<<<(FIN * FOUT + 255) / 256, 256>>>(Wm, Wv);       // launch 2
    deg_kernel<<<592, 256>>>(edst, E);                             // launch 3
    scan_kernel<<<1, 1024>>>(n, E);                                // launch 4

    cudaFuncSetAttribute(gemm_mma_kernel,
                         cudaFuncAttributeMaxDynamicSharedMemorySize,
                         SMEM_TOTAL);
    gemm_mma_kernel<<<(n + 127) / 128, 512, SMEM_TOTAL>>>(feat, n); // launch 5

    scatter_kernel<<<592, 256>>>(esrc, edst, E);                   // launch 6

    int warps_per_block = 512 / 32;
    int agg_blocks = (n + warps_per_block - 1) / warps_per_block;
    agg_csr_kernel<<<agg_blocks, 512>>>(out_mean, out_var, n);     // launch 7
}

// round 17
// speedup vs baseline: 1.6623x; 1.1008x over previous
#include <cuda_runtime.h>
#include <cuda_fp16.h>
#include <cstdint>
#include <cstddef>

#define N_MAX 50000
#define E_MAX 800000
#define FIN   256
#define FOUT  128
#define AST   72   // padded smem row stride (fp16 elems)

// ---------------------------------------------------------------------------
// Scratch (static device globals — no runtime allocation allowed)
// ---------------------------------------------------------------------------
__device__ __half g_mh[(size_t)N_MAX * FOUT];  // mean message (fp16)
__device__ __half g_vh[(size_t)N_MAX * FOUT];  // var  message (fp16)
__device__ int   g_cnt[N_MAX];
__device__ int   g_off[N_MAX + 1];
__device__ int   g_cur[N_MAX];
__device__ int   g_ssrc[E_MAX];
__device__ float g_norm1[N_MAX];
// Transposed fp16 weights: [n][k] layout, FOUT x FIN each
__device__ __half g_wmh[(size_t)FOUT * FIN];
__device__ __half g_wvh[(size_t)FOUT * FIN];

__device__ __forceinline__ uint32_t pack2h(float a, float b) {
    __half2 h = __floats2half2_rn(a, b);
    return *(uint32_t*)&h;
}

// m16n8k16 row.col fp16 MMA, f32 accumulate (sm_80+)
__device__ __forceinline__ void mma_f16(float* d,
    uint32_t a0, uint32_t a1, uint32_t a2, uint32_t a3,
    uint32_t b0, uint32_t b1)
{
    asm volatile(
        "mma.sync.aligned.m16n8k16.row.col.f32.f16.f16.f32 "
        "{%0,%1,%2,%3}, {%4,%5,%6,%7}, {%8,%9}, {%0,%1,%2,%3};\n"
        : "+f"(d[0]), "+f"(d[1]), "+f"(d[2]), "+f"(d[3])
        : "r"(a0), "r"(a1), "r"(a2), "r"(a3), "r"(b0), "r"(b1));
}

// ---------------------------------------------------------------------------
// Degree histogram / scan / scatter
// ---------------------------------------------------------------------------
__global__ void deg_kernel(const int* __restrict__ dst, int E) {
    for (int i = blockIdx.x * blockDim.x + threadIdx.x; i < E;
         i += gridDim.x * blockDim.x)
        atomicAdd(&g_cnt[dst[i]], 1);
}

__global__ void scan_kernel(int n, int E) {
    __shared__ int part[1024];
    const int t = threadIdx.x;
    const int chunk = (n + 1023) / 1024;
    const int beg = t * chunk;
    const int end = (beg + chunk < n) ? beg + chunk : n;
    int s = 0;
    for (int i = beg; i < end; i++) s += g_cnt[i];
    part[t] = s;
    __syncthreads();
    for (int off = 1; off < 1024; off <<= 1) {
        int tmp = (t >= off) ? part[t - off] : 0;
        __syncthreads();
        part[t] += tmp;
        __syncthreads();
    }
    int run = part[t] - s;
    for (int i = beg; i < end; i++) {
        g_off[i] = run;
        g_cur[i] = run;
        int c = g_cnt[i];
        run += c;
        float d = (float)((c < 1) ? 1 : c);
        g_norm1[i] = rsqrtf(d);
    }
    if (t == 1023) g_off[n] = E;
}

__global__ void scatter_kernel(const int* __restrict__ src,
                               const int* __restrict__ dst, int E) {
    for (int i = blockIdx.x * blockDim.x + threadIdx.x; i < E;
         i += gridDim.x * blockDim.x) {
        int d = dst[i];
        int pos = atomicAdd(&g_cur[d], 1);
        g_ssrc[pos] = src[i];
    }
}

// ---------------------------------------------------------------------------
// Weight prep: transpose to [n][k], fp32 -> fp16 (single term)
// ---------------------------------------------------------------------------
__global__ void wprep_kernel(const float* __restrict__ Wm,
                             const float* __restrict__ Wv) {
    int idx = blockIdx.x * blockDim.x + threadIdx.x;
    if (idx >= FIN * FOUT) return;
    int k = idx / FOUT, nn = idx % FOUT;
    size_t o = (size_t)nn * FIN + k;
    g_wmh[o] = __float2half_rn(Wm[idx]);
    g_wvh[o] = __float2half_rn(Wv[idx]);
}

// ---------------------------------------------------------------------------
// mma.sync fp16 dual-GEMM + message epilogue: 512 threads, 4m x 4n warps
// (32x32 warp tiles), double-buffered smem. Messages stored fp16.
// ---------------------------------------------------------------------------
#define SM_AH  0
#define SM_AL  18432
#define SM_MH  36864
#define SM_VH  55296
#define BUF_B  73728
#define SMEM_TOTAL (2 * BUF_B)   // 147456 B

__global__ void __launch_bounds__(512, 1) gemm_mma_kernel(
    const float* __restrict__ feat, int n)
{
    extern __shared__ char smem[];
    const int tid  = threadIdx.x;
    const int wid  = tid >> 5;
    const int lane = tid & 31;
    const int gid  = lane >> 2;
    const int tig  = lane & 3;
    const int wm   = wid >> 2;       // warp m 0..3
    const int wn   = wid & 3;        // warp n 0..3
    const int m0   = blockIdx.x * 128;

    float accM[2][4][4];
    float accV[2][4][4];
#pragma unroll
    for (int mt = 0; mt < 2; mt++)
#pragma unroll
        for (int nt = 0; nt < 4; nt++)
#pragma unroll
            for (int r = 0; r < 4; r++) { accM[mt][nt][r] = 0.f; accV[mt][nt][r] = 0.f; }

    float4 pf[4];   // A prefetch registers

    auto loadA = [&](int c) {
#pragma unroll
        for (int i = 0; i < 4; i++) {
            int idx = tid + i * 512;
            int row = idx >> 4;
            int c4  = (idx & 15) * 4;
            pf[i] = make_float4(0.f, 0.f, 0.f, 0.f);
            if (m0 + row < n)
                pf[i] = *(const float4*)(feat + (size_t)(m0 + row) * FIN + c * 64 + c4);
        }
    };
    auto cpasyncW = [&](int c, int buf) {
#pragma unroll
        for (int t2 = 0; t2 < 2; t2++) {
            const __half* src = t2 ? g_wvh : g_wmh;
            int off = buf * BUF_B + (t2 ? SM_VH : SM_MH);
#pragma unroll
            for (int i = 0; i < 4; i++) {
                int idx = tid + i * 512;
                int nn = idx >> 4;
                int k4 = (idx & 15) * 4;
                uint32_t saddr = (uint32_t)__cvta_generic_to_shared(
                    smem + off + (nn * AST + k4) * 2);
                const void* gaddr = src + (size_t)nn * FIN + c * 64 + k4;
                asm volatile("cp.async.ca.shared.global [%0], [%1], 8;"
                             :: "r"(saddr), "l"(gaddr));
            }
        }
        asm volatile("cp.async.commit_group;");
    };
    auto storeA = [&](int buf) {
#pragma unroll
        for (int i = 0; i < 4; i++) {
            int idx = tid + i * 512;
            int row = idx >> 4;
            int c4  = (idx & 15) * 4;
            float4 f = pf[i];
            float hx = __half2float(__float2half_rn(f.x));
            float hy = __half2float(__float2half_rn(f.y));
            float hz = __half2float(__float2half_rn(f.z));
            float hw = __half2float(__float2half_rn(f.w));
            uint2 hi = make_uint2(pack2h(f.x, f.y), pack2h(f.z, f.w));
            uint2 lo = make_uint2(pack2h(f.x - hx, f.y - hy),
                                  pack2h(f.z - hz, f.w - hw));
            int eo = buf * BUF_B + (row * AST + c4) * 2;
            *(uint2*)(smem + SM_AH + eo) = hi;
            *(uint2*)(smem + SM_AL + eo) = lo;
        }
    };

    loadA(0);
    cpasyncW(0, 0);
    storeA(0);
    asm volatile("cp.async.wait_group 0;");
    __syncthreads();

    int buf = 0;
#pragma unroll 1
    for (int c = 0; c < 4; c++) {
        int nbuf = buf ^ 1;
        if (c < 3) {
            loadA(c + 1);
            cpasyncW(c + 1, nbuf);
        }

        const int bo = buf * BUF_B;
#pragma unroll
        for (int ks = 0; ks < 4; ks++) {
            const int k0 = ks * 16;
            uint32_t ah[2][4], al[2][4];
#pragma unroll
            for (int mt = 0; mt < 2; mt++) {
                int base = bo + ((wm * 32 + mt * 16 + gid) * AST + k0 + 2 * tig) * 2;
                ah[mt][0] = *(const uint32_t*)(smem + SM_AH + base);
                ah[mt][1] = *(const uint32_t*)(smem + SM_AH + base + 8 * AST * 2);
                ah[mt][2] = *(const uint32_t*)(smem + SM_AH + base + 16);
                ah[mt][3] = *(const uint32_t*)(smem + SM_AH + base + 8 * AST * 2 + 16);
                al[mt][0] = *(const uint32_t*)(smem + SM_AL + base);
                al[mt][1] = *(const uint32_t*)(smem + SM_AL + base + 8 * AST * 2);
                al[mt][2] = *(const uint32_t*)(smem + SM_AL + base + 16);
                al[mt][3] = *(const uint32_t*)(smem + SM_AL + base + 8 * AST * 2 + 16);
            }
#pragma unroll
            for (int nt = 0; nt < 4; nt++) {
                int nb = bo + ((wn * 32 + nt * 8 + gid) * AST + k0 + 2 * tig) * 2;
                {
                    uint32_t b0 = *(const uint32_t*)(smem + SM_MH + nb);
                    uint32_t b1 = *(const uint32_t*)(smem + SM_MH + nb + 16);
#pragma unroll
                    for (int mt = 0; mt < 2; mt++) {
                        mma_f16(accM[mt][nt], ah[mt][0], ah[mt][1], ah[mt][2], ah[mt][3], b0, b1);
                        mma_f16(accM[mt][nt], al[mt][0], al[mt][1], al[mt][2], al[mt][3], b0, b1);
                    }
                }
                {
                    uint32_t b0 = *(const uint32_t*)(smem + SM_VH + nb);
                    uint32_t b1 = *(const uint32_t*)(smem + SM_VH + nb + 16);
#pragma unroll
                    for (int mt = 0; mt < 2; mt++) {
                        mma_f16(accV[mt][nt], ah[mt][0], ah[mt][1], ah[mt][2], ah[mt][3], b0, b1);
                        mma_f16(accV[mt][nt], al[mt][0], al[mt][1], al[mt][2], al[mt][3], b0, b1);
                    }
                }
            }
        }

        if (c < 3) {
            storeA(nbuf);
            asm volatile("cp.async.wait_group 0;");
        }
        __syncthreads();
        buf = nbuf;
    }

    // ---- epilogue: relu, attention, src-norm -> fp16 messages ----
#pragma unroll
    for (int mt = 0; mt < 2; mt++) {
#pragma unroll
        for (int rr = 0; rr < 2; rr++) {
            int row  = wm * 32 + mt * 16 + rr * 8 + gid;
            int node = m0 + row;
            if (node >= n) continue;
            float n1 = g_norm1[node];
            float n2 = n1 * n1;
            __half* pm = g_mh + (size_t)node * FOUT;
            __half* pv = g_vh + (size_t)node * FOUT;
#pragma unroll
            for (int nt = 0; nt < 4; nt++) {
                int col = wn * 32 + nt * 8 + 2 * tig;   // even
                float M0 = accM[mt][nt][rr * 2 + 0];
                float M1 = accM[mt][nt][rr * 2 + 1];
                float V0 = accV[mt][nt][rr * 2 + 0];
                float V1 = accV[mt][nt][rr * 2 + 1];
                float mean0 = fmaxf(M0, 0.f), var0 = fmaxf(V0, 0.f);
                float mean1 = fmaxf(M1, 0.f), var1 = fmaxf(V1, 0.f);
                float att0 = __expf(-var0), att1 = __expf(-var1);
                *(uint32_t*)(pm + col) = pack2h(mean0 * att0 * n1, mean1 * att1 * n1);
                *(uint32_t*)(pv + col) = pack2h(var0 * att0 * att0 * n2,
                                                var1 * att1 * att1 * n2);
            }
        }
    }
}

// ---------------------------------------------------------------------------
// CSR aggregation: one warp per dst node; fp16 message gather, fp32 accumulate.
// Each lane owns 4 columns (lane*4): one uint2 (4 halfs) per array per edge.
// ---------------------------------------------------------------------------
__global__ void agg_csr_kernel(float* __restrict__ out_mean,
                               float* __restrict__ out_var,
                               int n)
{
    int w    = (int)((blockIdx.x * (size_t)blockDim.x + threadIdx.x) >> 5);
    int lane = threadIdx.x & 31;
    if (w >= n) return;

    int b = g_off[w];
    int e = g_off[w + 1];
    const int c4 = lane * 4;

    float4 am = make_float4(0.0f, 0.0f, 0.0f, 0.0f);
    float4 av = make_float4(0.0f, 0.0f, 0.0f, 0.0f);

    auto accum = [&](int s) {
        uint2 mr = *(const uint2*)(g_mh + (size_t)s * FOUT + c4);
        uint2 vr = *(const uint2*)(g_vh + (size_t)s * FOUT + c4);
        float2 m0 = __half22float2(*(__half2*)&mr.x);
        float2 m1 = __half22float2(*(__half2*)&mr.y);
        float2 v0 = __half22float2(*(__half2*)&vr.x);
        float2 v1 = __half22float2(*(__half2*)&vr.y);
        am.x += m0.x; am.y += m0.y; am.z += m1.x; am.w += m1.y;
        av.x += v0.x; av.y += v0.y; av.z += v1.x; av.w += v1.y;
    };

    int i = b;
    for (; i + 2 <= e; i += 2) {
        int s0 = __ldg(g_ssrc + i);
        int s1 = __ldg(g_ssrc + i + 1);
        accum(s0);
        accum(s1);
    }
    if (i < e) accum(__ldg(g_ssrc + i));

    float n1 = g_norm1[w];
    float n2 = n1 * n1;
    am.x *= n1; am.y *= n1; am.z *= n1; am.w *= n1;
    av.x *= n2; av.y *= n2; av.z *= n2; av.w *= n2;

    *(float4*)(out_mean + (size_t)w * FOUT + c4) = am;
    *(float4*)(out_var  + (size_t)w * FOUT + c4) = av;
}

// ---------------------------------------------------------------------------
// Launch — GEMM kept at launch #5 for ncu's "-s 5 -c 1" capture.
// ---------------------------------------------------------------------------
extern "C" void kernel_launch(void* const* d_in, const int* in_sizes, int n_in,
                              void* d_out, int out_size)
{
    const float* feat = (const float*)d_in[0];
    const int*   esrc = (const int*)d_in[1];
    const int*   edst = (const int*)d_in[2];
    const float* Wm   = (const float*)d_in[3];
    const float* Wv   = (const float*)d_in[4];
    float* out = (float*)d_out;

    int n = in_sizes[0] / FIN;   // 50000
    int E = in_sizes[1];         // 800000

    float* out_mean = out;
    float* out_var  = out + (size_t)n * FOUT;

    void* cnt_ptr = nullptr;
    cudaGetSymbolAddress(&cnt_ptr, g_cnt);
    cudaMemsetAsync(cnt_ptr, 0, (size_t)N_MAX * sizeof(int));      // launch 1

    wprep_kernel<<<(FIN * FOUT + 255) / 256, 256>>>(Wm, Wv);       // launch 2
    deg_kernel<<<592, 256>>>(edst, E);                             // launch 3
    scan_kernel<<<1, 1024>>>(n, E);                                // launch 4

    cudaFuncSetAttribute(gemm_mma_kernel,
                         cudaFuncAttributeMaxDynamicSharedMemorySize,
                         SMEM_TOTAL);
    gemm_mma_kernel<<<(n + 127) / 128, 512, SMEM_TOTAL>>>(feat, n); // launch 5

    scatter_kernel<<<592, 256>>>(esrc, edst, E);                   // launch 6

    int warps_per_block = 512 / 32;
    int agg_blocks = (n + warps_per_block - 1) / warps_per_block;
    agg_csr_kernel<<<agg_blocks, 512>>>(out_mean, out_var, n);     // launch 7
}